// round 11
// baseline (speedup 1.0000x reference)
#include <cuda_runtime.h>
#include <cuda_bf16.h>
#include <stdint.h>
#include <math.h>

#define FEAT  512
#define NCLS  100000
#define NROW  512
#define BM    128
#define BN    128
#define NCT   782
#define NRT   4
#define CTP   782
#define NCH   8

#define C_COS_M   0.87758256189037276f
#define C_SIN_M   0.47942553860420301f
#define C_THRESH  (-0.87758256189037276f)
#define C_MM      0.23971276930210156f
#define C_S       64.0f
#define C_EPS     0.1f

// ---- scratch ----
__device__ float          g_e[NROW * FEAT];
__device__ __nv_bfloat16  g_ebfT[FEAT * NROW];   // [k][m] bf16
__device__ float g_tl[NROW];
__device__ float g_ctm[NROW];
__device__ float g_ft[NROW];
__device__ float g_t;
__device__ float g_pm[NROW * CTP];
__device__ float g_ps[NROW * CTP];
__device__ float g_psl[NROW * CTP];
__device__ float g_rowloss[NROW];

// =================== helpers ===================
__device__ __forceinline__ void cp16(uint32_t dst, const void* src) {
    asm volatile("cp.async.cg.shared.global [%0], [%1], 16;" :: "r"(dst), "l"(src));
}
__device__ __forceinline__ void cp16z(uint32_t dst, const void* src, int nbytes) {
    asm volatile("cp.async.cg.shared.global [%0], [%1], 16, %2;"
                 :: "r"(dst), "l"(src), "r"(nbytes));
}
__device__ __forceinline__ uint32_t s2u(const void* p) {
    uint32_t a;
    asm("{ .reg .u64 t; cvta.to.shared.u64 t, %1; cvt.u32.u64 %0, t; }" : "=r"(a) : "l"(p));
    return a;
}
// [k][c] bf16 tile, 256B rows; 16B-chunk XOR swizzle by k (verified round 9)
__device__ __forceinline__ uint32_t bswz(int k, int c) {
    return (uint32_t)(k * 256 + ((((c >> 3) ^ k) & 7) << 4) + ((c >> 3) & 8) * 16 + (c & 7) * 2);
}
__device__ __forceinline__ void ldsm4t(uint32_t* a, uint32_t addr) {
    asm volatile("ldmatrix.sync.aligned.m8n8.x4.trans.shared.b16 {%0,%1,%2,%3}, [%4];"
                 : "=r"(a[0]), "=r"(a[1]), "=r"(a[2]), "=r"(a[3]) : "r"(addr));
}
__device__ __forceinline__ void mma16816(float* c, const uint32_t* a, const uint32_t* b) {
    asm volatile(
        "mma.sync.aligned.m16n8k16.row.col.f32.bf16.bf16.f32 "
        "{%0,%1,%2,%3}, {%4,%5,%6,%7}, {%8,%9}, {%0,%1,%2,%3};"
        : "+f"(c[0]), "+f"(c[1]), "+f"(c[2]), "+f"(c[3])
        : "r"(a[0]), "r"(a[1]), "r"(a[2]), "r"(a[3]), "r"(b[0]), "r"(b[1]));
}

// =================== K1: row-normalize e (writes transposed bf16) ===================
__global__ void k_norm_e(const float* __restrict__ emb) {
    int r = blockIdx.x, t = threadIdx.x;   // 512 x 128
    float v[4], s = 0.f;
#pragma unroll
    for (int i = 0; i < 4; i++) { v[i] = emb[r * FEAT + t + i * 128]; s += v[i] * v[i]; }
#pragma unroll
    for (int o = 16; o; o >>= 1) s += __shfl_xor_sync(0xffffffffu, s, o);
    __shared__ float sm[4];
    if ((t & 31) == 0) sm[t >> 5] = s;
    __syncthreads();
    float inv = rsqrtf(sm[0] + sm[1] + sm[2] + sm[3]);
#pragma unroll
    for (int i = 0; i < 4; i++) {
        float x = v[i] * inv;
        int k = t + i * 128;
        g_e[r * FEAT + k] = x;
        g_ebfT[(size_t)k * NROW + r] = __float2bfloat16(x);
    }
}

// =================== K2: target logits + ctm/ft ===================
__global__ void k_target(const float* __restrict__ w, const int* __restrict__ label) {
    int gw = (blockIdx.x * blockDim.x + threadIdx.x) >> 5;
    int lane = threadIdx.x & 31;
    if (gw >= NROW) return;
    int lab = label[gw];
    const float* e = g_e + gw * FEAT;
    float dot = 0.f, sq = 0.f;
#pragma unroll
    for (int j = 0; j < 16; j++) {
        int k = lane + 32 * j;
        float wv = w[(size_t)k * NCLS + lab];
        dot += e[k] * wv;
        sq  += wv * wv;
    }
#pragma unroll
    for (int o = 16; o; o >>= 1) {
        dot += __shfl_xor_sync(0xffffffffu, dot, o);
        sq  += __shfl_xor_sync(0xffffffffu, sq, o);
    }
    if (lane == 0) {
        float tl = fminf(1.0f, fmaxf(-1.0f, dot * rsqrtf(sq)));
        g_tl[gw] = tl;
        float sint = sqrtf(fmaxf(0.f, 1.0f - tl * tl));
        float ctm = tl * C_COS_M - sint * C_SIN_M;
        g_ctm[gw] = ctm;
        g_ft[gw] = (tl > C_THRESH) ? ctm : (tl - C_MM);
    }
}

// =================== K3: g_t ===================
__global__ void k_prep() {
    int i = threadIdx.x;
    float s = g_tl[i];
#pragma unroll
    for (int o = 16; o; o >>= 1) s += __shfl_xor_sync(0xffffffffu, s, o);
    __shared__ float sm[16];
    if ((i & 31) == 0) sm[i >> 5] = s;
    __syncthreads();
    if (i < 16) {
        float v = sm[i];
#pragma unroll
        for (int o = 8; o; o >>= 1) v += __shfl_xor_sync(0x0000ffffu, v, o);
        if (i == 0) g_t = 0.01f * (v / (float)NROW);
    }
}

// =================== K4: fused GEMM ===================
// smem: A[k][m] bf16 [2][16KB] @0, B[k][c] bf16 [2][16KB] @32K, f32 staging 32KB @64K
#define SMBB0   32768
#define SMST    65536
#define SMSZ    98304

__global__ void __launch_bounds__(256, 2) k_gemm(const int* __restrict__ label,
                                                 const float* __restrict__ w) {
    extern __shared__ char smdy[];
    uint32_t sb = s2u(smdy);
    const int tid = threadIdx.x, lane = tid & 31, wid = tid >> 5;
    const int warpM = wid >> 2;
    const int warpN = wid & 3;
    const int r0 = blockIdx.x * BM;
    const int c0 = blockIdx.y * BN;

    // conversion/load thread mapping
    const int cvk  = tid >> 5;             // k slot 0..7
    const int cvc  = lane * 4;             // column quad
    const int wvalid = (c0 + cvc < NCLS);
    const int wbytes = wvalid ? 16 : 0;
    const size_t wcol = wvalid ? (size_t)(c0 + cvc) : 0;
    const int ak   = tid >> 4;             // A-load k slot 0..15
    const int aseg = tid & 15;

    // precomputed ldsm base addresses (buffer 0, ks 0)
    uint32_t aAddr[4], bAddr[2];
    {
        int t = lane >> 3, rr = lane & 7;
        int kkA = (t >> 1) * 8 + rr;
        int kkB = (t & 1) * 8 + rr;
#pragma unroll
        for (int mt = 0; mt < 4; mt++)
            aAddr[mt] = sb + bswz(kkA, warpM * 64 + mt * 16 + (t & 1) * 8);
#pragma unroll
        for (int pr = 0; pr < 2; pr++)
            bAddr[pr] = sb + SMBB0 + bswz(kkB, warpN * 32 + pr * 16 + (t >> 1) * 8);
    }
    const uint32_t stAddr = sb + SMST + cvk * 512 + lane * 16;
    const uint32_t bstAddr = sb + SMBB0 + bswz(cvk, cvc);   // +2048 per p, +16384 stage
    const uint32_t astAddr = sb + bswz(ak, aseg * 8);       // +4096 per u, +16384 stage

    float acc[4][4][4];
#pragma unroll
    for (int a = 0; a < 4; a++)
#pragma unroll
        for (int b = 0; b < 4; b++)
#pragma unroll
            for (int c = 0; c < 4; c++) acc[a][b][c] = 0.f;
    float sq4[4] = {0.f, 0.f, 0.f, 0.f};

#define LOAD_STAGE(chunk) do {                                                   \
        const float* _ws = w + (size_t)((chunk) * 64 + cvk) * NCLS + wcol;       \
        uint32_t _wd = stAddr;                                                   \
        _Pragma("unroll")                                                        \
        for (int u = 0; u < 8; u++) {                                            \
            cp16z(_wd, _ws, wbytes);                                             \
            _ws += (size_t)8 * NCLS; _wd += 4096;                                \
        }                                                                        \
        const __nv_bfloat16* _as = g_ebfT + (size_t)((chunk) * 64 + ak) * NROW + r0 + aseg * 8; \
        uint32_t _ad = astAddr + ((chunk) & 1) * 16384;                          \
        _Pragma("unroll")                                                        \
        for (int u = 0; u < 4; u++) {                                            \
            cp16(_ad, _as);                                                      \
            _as += (size_t)16 * NROW; _ad += 4096;                               \
        }                                                                        \
        asm volatile("cp.async.commit_group;");                                  \
    } while (0)

#define CVT_BATCH(pbase, s) do {                                                 \
        float4 _v[4];                                                            \
        _Pragma("unroll")                                                        \
        for (int p = 0; p < 4; p++)                                              \
            _v[p] = *(const float4*)(smdy + (stAddr - sb) + ((pbase) + p) * 4096); \
        _Pragma("unroll")                                                        \
        for (int p = 0; p < 4; p++) {                                            \
            sq4[0] += _v[p].x * _v[p].x; sq4[1] += _v[p].y * _v[p].y;            \
            sq4[2] += _v[p].z * _v[p].z; sq4[3] += _v[p].w * _v[p].w;            \
            __nv_bfloat162 _p0 = __floats2bfloat162_rn(_v[p].x, _v[p].y);        \
            __nv_bfloat162 _p1 = __floats2bfloat162_rn(_v[p].z, _v[p].w);        \
            uint2 _u2; _u2.x = *(uint32_t*)&_p0; _u2.y = *(uint32_t*)&_p1;       \
            *(uint2*)(smdy + (bstAddr - sb) + (s) * 16384 + ((pbase) + p) * 2048) = _u2; \
        }                                                                        \
    } while (0)

#define MMA_HALF(s, h) do {                                                      \
        _Pragma("unroll")                                                        \
        for (int ks = (h) * 2; ks < (h) * 2 + 2; ks++) {                         \
            uint32_t bf[2][4];                                                   \
            ldsm4t(bf[0], bAddr[0] + (s) * 16384 + ks * 4096);                   \
            ldsm4t(bf[1], bAddr[1] + (s) * 16384 + ks * 4096);                   \
            _Pragma("unroll")                                                    \
            for (int mt = 0; mt < 4; mt++) {                                     \
                uint32_t af[4];                                                  \
                ldsm4t(af, aAddr[mt] + (s) * 16384 + ks * 4096);                 \
                mma16816(acc[mt][0], af, &bf[0][0]);                             \
                mma16816(acc[mt][1], af, &bf[0][2]);                             \
                mma16816(acc[mt][2], af, &bf[1][0]);                             \
                mma16816(acc[mt][3], af, &bf[1][2]);                             \
            }                                                                    \
        }                                                                        \
    } while (0)

    // prologue: chunk 0
    LOAD_STAGE(0);
    asm volatile("cp.async.wait_group 0;");
    __syncthreads();
    CVT_BATCH(0, 0);
    CVT_BATCH(4, 0);
    __syncthreads();
    LOAD_STAGE(1);

#pragma unroll 1
    for (int it = 1; it < NCH; it++) {
        int s = it & 1, sp = s ^ 1;
        asm volatile("cp.async.wait_group 0;");
        __syncthreads();
        CVT_BATCH(0, s);       // convert chunk it (hides under mma below)
        MMA_HALF(sp, 0);       // mma chunk it-1
        CVT_BATCH(4, s);
        MMA_HALF(sp, 1);
        __syncthreads();
        if (it < NCH - 1) LOAD_STAGE(it + 1);
    }
    // tail: mma chunk 7 (buffers parity 1)
    MMA_HALF(1, 0);
    MMA_HALF(1, 1);
    __syncthreads();

    // ---- column inv-norms from in-kernel sums ----
    float* sums = (float*)(smdy + SMST);   // [8][128]
#pragma unroll
    for (int j = 0; j < 4; j++) sums[cvk * 128 + cvc + j] = sq4[j];
    __syncthreads();

    float* smf = (float*)smdy;
    int*   smi = (int*)smdy;
    if (tid < 128) {
        float z = 0.f;
#pragma unroll
        for (int s8 = 0; s8 < 8; s8++) z += sums[s8 * 128 + tid];
        smf[tid] = rsqrtf(z);
        int r = r0 + tid;
        smf[128 + tid] = g_ctm[r];
        smf[256 + tid] = g_ft[r];
        smi[384 + tid] = label[r];
    }
    __syncthreads();

    const float tad = g_t;
    const int g = lane >> 2, q = lane & 3;
#pragma unroll
    for (int mt = 0; mt < 4; mt++) {
#pragma unroll
        for (int half = 0; half < 2; half++) {
            int rl = warpM * 64 + mt * 16 + g + half * 8;
            float ctm = smf[128 + rl], ft = smf[256 + rl];
            int lab = smi[384 + rl];
            float L[8];
            float mx = -3.0e38f;
#pragma unroll
            for (int nt = 0; nt < 4; nt++) {
#pragma unroll
                for (int b = 0; b < 2; b++) {
                    int cl = warpN * 32 + nt * 8 + q * 2 + b;
                    int c = c0 + cl;
                    float Lv;
                    if (c < NCLS) {
                        float cv = acc[mt][nt][half * 2 + b] * smf[cl];
                        cv = fminf(1.f, fmaxf(-1.f, cv));
                        if (c == lab) {
                            Lv = C_S * ft;
                        } else {
                            if (cv > ctm) cv = cv * (tad + cv);
                            Lv = C_S * cv;
                        }
                        mx = fmaxf(mx, Lv);
                    } else {
                        Lv = -3.0e38f;
                    }
                    L[nt * 2 + b] = Lv;
                }
            }
            mx = fmaxf(mx, __shfl_xor_sync(0xffffffffu, mx, 1));
            mx = fmaxf(mx, __shfl_xor_sync(0xffffffffu, mx, 2));
            float s = 0.f, sl = 0.f;
#pragma unroll
            for (int j = 0; j < 8; j++) {
                if (L[j] > -1.0e38f) { s += __expf(L[j] - mx); sl += L[j]; }
            }
            s  += __shfl_xor_sync(0xffffffffu, s, 1);
            s  += __shfl_xor_sync(0xffffffffu, s, 2);
            sl += __shfl_xor_sync(0xffffffffu, sl, 1);
            sl += __shfl_xor_sync(0xffffffffu, sl, 2);
            if (q == 0) {
                smf[512  + warpN * 128 + rl] = mx;
                smf[1024 + warpN * 128 + rl] = s;
                smf[1536 + warpN * 128 + rl] = sl;
            }
        }
    }
    __syncthreads();

    if (tid < 128) {
        float m = -3.0e38f;
#pragma unroll
        for (int wn = 0; wn < 4; wn++) m = fmaxf(m, smf[512 + wn * 128 + tid]);
        float s = 0.f, sl = 0.f;
#pragma unroll
        for (int wn = 0; wn < 4; wn++) {
            float mw = smf[512 + wn * 128 + tid];
            if (mw > -1.0e38f) s += smf[1024 + wn * 128 + tid] * __expf(mw - m);
            sl += smf[1536 + wn * 128 + tid];
        }
        int slot = (r0 + tid) * CTP + blockIdx.y;
        g_pm[slot] = m;
        g_ps[slot] = s;
        g_psl[slot] = sl;
    }
}

// =================== K5: merge partials per row ===================
__global__ void k_rowreduce() {
    int r = blockIdx.x;
    int tid = threadIdx.x;
    float m = -3.0e38f, s = 0.f, sl = 0.f;
    for (int ct = tid; ct < CTP; ct += 256) {
        float m2 = g_pm[r * CTP + ct];
        float s2 = g_ps[r * CTP + ct];
        sl += g_psl[r * CTP + ct];
        if (m2 > m) { s = s * __expf(m - m2) + s2; m = m2; }
        else        { s += s2 * __expf(m2 - m); }
    }
    __shared__ float sm_m[256], sm_s[256], sm_sl[256];
    sm_m[tid] = m; sm_s[tid] = s; sm_sl[tid] = sl;
    __syncthreads();
    for (int o = 128; o; o >>= 1) {
        if (tid < o) {
            float m1 = sm_m[tid], s1 = sm_s[tid];
            float m2 = sm_m[tid + o], s2 = sm_s[tid + o];
            float M = fmaxf(m1, m2);
            sm_s[tid] = s1 * __expf(m1 - M) + s2 * __expf(m2 - M);
            sm_m[tid] = M;
            sm_sl[tid] += sm_sl[tid + o];
        }
        __syncthreads();
    }
    if (tid == 0) {
        float LSE = sm_m[0] + logf(sm_s[0]);
        float nll = LSE - C_S * g_ft[r];
        float smooth = LSE - sm_sl[0] / (float)NCLS;
        g_rowloss[r] = (1.0f - C_EPS) * nll + C_EPS * smooth;
    }
}

// =================== K6: mean ===================
__global__ void k_final(float* __restrict__ out) {
    int tid = threadIdx.x;
    float v = g_rowloss[tid];
#pragma unroll
    for (int o = 16; o; o >>= 1) v += __shfl_xor_sync(0xffffffffu, v, o);
    __shared__ float sm[16];
    if ((tid & 31) == 0) sm[tid >> 5] = v;
    __syncthreads();
    if (tid < 16) {
        float x = sm[tid];
#pragma unroll
        for (int o = 8; o; o >>= 1) x += __shfl_xor_sync(0x0000ffffu, x, o);
        if (tid == 0) out[0] = x / (float)NROW;
    }
}

// ===================================================
extern "C" void kernel_launch(void* const* d_in, const int* in_sizes, int n_in,
                              void* d_out, int out_size) {
    const float* emb = (const float*)d_in[0];
    const float* w = (const float*)d_in[1];
    const int* label = (const int*)d_in[2];
    float* out = (float*)d_out;

    cudaFuncSetAttribute(k_gemm, cudaFuncAttributeMaxDynamicSharedMemorySize, SMSZ);

    k_norm_e<<<NROW, 128>>>(emb);
    k_target<<<64, 256>>>(w, label);
    k_prep<<<1, NROW>>>();
    k_gemm<<<dim3(NRT, NCT), 256, SMSZ>>>(label, w);
    k_rowreduce<<<NROW, 256>>>();
    k_final<<<1, NROW>>>(out);
}

// round 12
// speedup vs baseline: 1.1059x; 1.1059x over previous
#include <cuda_runtime.h>
#include <cuda_bf16.h>
#include <stdint.h>
#include <math.h>

#define FEAT  512
#define NCLS  100000
#define NROW  512
#define BM    128
#define BN    128
#define NCT   782
#define NRT   4
#define CTP   782
#define CK    32
#define NCH16 16

#define C_COS_M   0.87758256189037276f
#define C_SIN_M   0.47942553860420301f
#define C_THRESH  (-0.87758256189037276f)
#define C_MM      0.23971276930210156f
#define C_S       64.0f
#define C_EPS     0.1f

// ---- scratch ----
__device__ float          g_e[NROW * FEAT];
__device__ __nv_bfloat16  g_ebfT[FEAT * NROW];   // [k][m] bf16
__device__ float g_tl[NROW];
__device__ float g_ctm[NROW];
__device__ float g_ft[NROW];
__device__ float g_t;
__device__ float g_pm[NROW * CTP];
__device__ float g_ps[NROW * CTP];
__device__ float g_psl[NROW * CTP];
__device__ float g_rowloss[NROW];

// =================== helpers ===================
__device__ __forceinline__ void cp16(uint32_t dst, const void* src) {
    asm volatile("cp.async.cg.shared.global [%0], [%1], 16;" :: "r"(dst), "l"(src));
}
__device__ __forceinline__ void cp16z(uint32_t dst, const void* src, int nbytes) {
    asm volatile("cp.async.cg.shared.global [%0], [%1], 16, %2;"
                 :: "r"(dst), "l"(src), "r"(nbytes));
}
__device__ __forceinline__ uint32_t s2u(const void* p) {
    uint32_t a;
    asm("{ .reg .u64 t; cvta.to.shared.u64 t, %1; cvt.u32.u64 %0, t; }" : "=r"(a) : "l"(p));
    return a;
}
// [k][c] bf16 tile, 256B rows; 16B-chunk XOR swizzle by k (verified rounds 9/11)
__device__ __forceinline__ uint32_t bswz(int k, int c) {
    return (uint32_t)(k * 256 + ((((c >> 3) ^ k) & 7) << 4) + ((c >> 3) & 8) * 16 + (c & 7) * 2);
}
__device__ __forceinline__ void ldsm4t(uint32_t* a, uint32_t addr) {
    asm volatile("ldmatrix.sync.aligned.m8n8.x4.trans.shared.b16 {%0,%1,%2,%3}, [%4];"
                 : "=r"(a[0]), "=r"(a[1]), "=r"(a[2]), "=r"(a[3]) : "r"(addr));
}
__device__ __forceinline__ void mma16816(float* c, const uint32_t* a, const uint32_t* b) {
    asm volatile(
        "mma.sync.aligned.m16n8k16.row.col.f32.bf16.bf16.f32 "
        "{%0,%1,%2,%3}, {%4,%5,%6,%7}, {%8,%9}, {%0,%1,%2,%3};"
        : "+f"(c[0]), "+f"(c[1]), "+f"(c[2]), "+f"(c[3])
        : "r"(a[0]), "r"(a[1]), "r"(a[2]), "r"(a[3]), "r"(b[0]), "r"(b[1]));
}

// =================== K1: row-normalize e (writes transposed bf16) ===================
__global__ void k_norm_e(const float* __restrict__ emb) {
    int r = blockIdx.x, t = threadIdx.x;   // 512 x 128
    float v[4], s = 0.f;
#pragma unroll
    for (int i = 0; i < 4; i++) { v[i] = emb[r * FEAT + t + i * 128]; s += v[i] * v[i]; }
#pragma unroll
    for (int o = 16; o; o >>= 1) s += __shfl_xor_sync(0xffffffffu, s, o);
    __shared__ float sm[4];
    if ((t & 31) == 0) sm[t >> 5] = s;
    __syncthreads();
    float inv = rsqrtf(sm[0] + sm[1] + sm[2] + sm[3]);
#pragma unroll
    for (int i = 0; i < 4; i++) {
        float x = v[i] * inv;
        int k = t + i * 128;
        g_e[r * FEAT + k] = x;
        g_ebfT[(size_t)k * NROW + r] = __float2bfloat16(x);
    }
}

// =================== K2: target logits + ctm/ft ===================
__global__ void k_target(const float* __restrict__ w, const int* __restrict__ label) {
    int gw = (blockIdx.x * blockDim.x + threadIdx.x) >> 5;
    int lane = threadIdx.x & 31;
    if (gw >= NROW) return;
    int lab = label[gw];
    const float* e = g_e + gw * FEAT;
    float dot = 0.f, sq = 0.f;
#pragma unroll
    for (int j = 0; j < 16; j++) {
        int k = lane + 32 * j;
        float wv = w[(size_t)k * NCLS + lab];
        dot += e[k] * wv;
        sq  += wv * wv;
    }
#pragma unroll
    for (int o = 16; o; o >>= 1) {
        dot += __shfl_xor_sync(0xffffffffu, dot, o);
        sq  += __shfl_xor_sync(0xffffffffu, sq, o);
    }
    if (lane == 0) {
        float tl = fminf(1.0f, fmaxf(-1.0f, dot * rsqrtf(sq)));
        g_tl[gw] = tl;
        float sint = sqrtf(fmaxf(0.f, 1.0f - tl * tl));
        float ctm = tl * C_COS_M - sint * C_SIN_M;
        g_ctm[gw] = ctm;
        g_ft[gw] = (tl > C_THRESH) ? ctm : (tl - C_MM);
    }
}

// =================== K3: g_t ===================
__global__ void k_prep() {
    int i = threadIdx.x;
    float s = g_tl[i];
#pragma unroll
    for (int o = 16; o; o >>= 1) s += __shfl_xor_sync(0xffffffffu, s, o);
    __shared__ float sm[16];
    if ((i & 31) == 0) sm[i >> 5] = s;
    __syncthreads();
    if (i < 16) {
        float v = sm[i];
#pragma unroll
        for (int o = 8; o; o >>= 1) v += __shfl_xor_sync(0x0000ffffu, v, o);
        if (i == 0) g_t = 0.01f * (v / (float)NROW);
    }
}

// =================== K4: fused GEMM, deep pipeline ===================
// smem: A[k32][m128] bf16 4 stages @0 (32KB), B[k32][c128] bf16 3 stages @32K (24KB),
//       f32 staging [k32][c128] 3 stages @56K (48KB)  => 104KB
#define SM_A   0
#define SM_B   32768
#define SM_ST  57344
#define SMSZ   106496

__global__ void __launch_bounds__(256, 2) k_gemm(const int* __restrict__ label,
                                                 const float* __restrict__ w) {
    extern __shared__ char smdy[];
    uint32_t sb = s2u(smdy);
    const int tid = threadIdx.x, lane = tid & 31, wid = tid >> 5;
    const int warpM = wid >> 2;
    const int warpN = wid & 3;
    const int r0 = blockIdx.x * BM;
    const int c0 = blockIdx.y * BN;

    // load / convert mappings
    const int wk = tid >> 5;               // staging k base (k = wk + u*8)
    const int wvalid = (c0 + lane * 4 < NCLS);
    const int wbytes = wvalid ? 16 : 0;
    const size_t wcol = wvalid ? (size_t)(c0 + lane * 4) : 0;
    const int ak = tid >> 4;               // A k base (k = ak + u*16)
    const int aseg = tid & 15;             // m seg

    const uint32_t stDst = sb + SM_ST + wk * 512 + lane * 16;   // +u*4096, +st3*16384
    const uint32_t aDst  = sb + SM_A + bswz(ak, aseg * 8);      // +u*4096, +st4*8192
    const uint32_t cvDst = sb + SM_B + bswz(wk, lane * 4);      // +u*2048, +st3*8192

    // ldsm base addresses (stage 0, h 0)
    uint32_t aAddr[4], bAddr[2];
    {
        int t = lane >> 3, rr = lane & 7;
        int kkA = (t >> 1) * 8 + rr;
        int kkB = (t & 1) * 8 + rr;
#pragma unroll
        for (int mt = 0; mt < 4; mt++)
            aAddr[mt] = sb + SM_A + bswz(kkA, warpM * 64 + mt * 16 + (t & 1) * 8);
#pragma unroll
        for (int pr = 0; pr < 2; pr++)
            bAddr[pr] = sb + SM_B + bswz(kkB, warpN * 32 + pr * 16 + (t >> 1) * 8);
    }

    float acc[4][4][4];
#pragma unroll
    for (int a = 0; a < 4; a++)
#pragma unroll
        for (int b = 0; b < 4; b++)
#pragma unroll
            for (int c = 0; c < 4; c++) acc[a][b][c] = 0.f;
    float sq4[4] = {0.f, 0.f, 0.f, 0.f};

#define LOADC(chunk, st3, st4) do {                                              \
        if ((chunk) < NCH16) {                                                   \
            const float* _ws = w + (size_t)((chunk) * CK + wk) * NCLS + wcol;    \
            uint32_t _wd = stDst + (st3) * 16384;                                \
            _Pragma("unroll")                                                    \
            for (int u = 0; u < 4; u++) {                                        \
                cp16z(_wd, _ws, wbytes);                                         \
                _ws += (size_t)8 * NCLS; _wd += 4096;                            \
            }                                                                    \
            const __nv_bfloat16* _as = g_ebfT + (size_t)((chunk) * CK + ak) * NROW + r0 + aseg * 8; \
            uint32_t _ad = aDst + (st4) * 8192;                                  \
            _Pragma("unroll")                                                    \
            for (int u = 0; u < 2; u++) {                                        \
                cp16(_ad, _as);                                                  \
                _as += (size_t)16 * NROW; _ad += 4096;                           \
            }                                                                    \
        }                                                                        \
        asm volatile("cp.async.commit_group;");                                  \
    } while (0)

#define CVTC(st3) do {                                                           \
        float4 _v[4];                                                            \
        _Pragma("unroll")                                                        \
        for (int u = 0; u < 4; u++)                                              \
            _v[u] = *(const float4*)(smdy + (stDst - sb) + (st3) * 16384 + u * 4096); \
        _Pragma("unroll")                                                        \
        for (int u = 0; u < 4; u++) {                                            \
            sq4[0] += _v[u].x * _v[u].x; sq4[1] += _v[u].y * _v[u].y;            \
            sq4[2] += _v[u].z * _v[u].z; sq4[3] += _v[u].w * _v[u].w;            \
            __nv_bfloat162 _p0 = __floats2bfloat162_rn(_v[u].x, _v[u].y);        \
            __nv_bfloat162 _p1 = __floats2bfloat162_rn(_v[u].z, _v[u].w);        \
            uint2 _u2; _u2.x = *(uint32_t*)&_p0; _u2.y = *(uint32_t*)&_p1;       \
            *(uint2*)(smdy + (cvDst - sb) + (st3) * 8192 + u * 2048) = _u2;      \
        }                                                                        \
    } while (0)

#define MMAC(st3, st4) do {                                                      \
        _Pragma("unroll")                                                        \
        for (int h = 0; h < 2; h++) {                                            \
            uint32_t bf[2][4];                                                   \
            ldsm4t(bf[0], bAddr[0] + (st3) * 8192 + h * 4096);                   \
            ldsm4t(bf[1], bAddr[1] + (st3) * 8192 + h * 4096);                   \
            _Pragma("unroll")                                                    \
            for (int mt = 0; mt < 4; mt++) {                                     \
                uint32_t af[4];                                                  \
                ldsm4t(af, aAddr[mt] + (st4) * 8192 + h * 4096);                 \
                mma16816(acc[mt][0], af, &bf[0][0]);                             \
                mma16816(acc[mt][1], af, &bf[0][2]);                             \
                mma16816(acc[mt][2], af, &bf[1][0]);                             \
                mma16816(acc[mt][3], af, &bf[1][2]);                             \
            }                                                                    \
        }                                                                        \
    } while (0)

    // prologue: 3 chunks in flight
    LOADC(0, 0, 0);
    LOADC(1, 1, 1);
    LOADC(2, 2, 2);

    int st3 = 0, st4u = 0, st4l = 3;
#pragma unroll 1
    for (int it = 0; it < NCH16; it++) {
        asm volatile("cp.async.wait_group 2;");
        __syncthreads();
        CVTC(st3);                     // staging[st3] -> B[st3]
        __syncthreads();
        LOADC(it + 3, st3, st4l);      // refill staging[st3], A[st4l]; streams under MMA
        MMAC(st3, st4u);
        st3 = (st3 == 2) ? 0 : st3 + 1;
        st4u = (st4u + 1) & 3;
        st4l = (st4l + 1) & 3;
    }
    __syncthreads();

    // ---- column inv-norms from in-kernel sums ----
    float* sums = (float*)(smdy + SM_ST);  // [8][128]
#pragma unroll
    for (int j = 0; j < 4; j++) sums[wk * 128 + lane * 4 + j] = sq4[j];
    __syncthreads();

    float* smf = (float*)smdy;
    int*   smi = (int*)smdy;
    if (tid < 128) {
        float z = 0.f;
#pragma unroll
        for (int s8 = 0; s8 < 8; s8++) z += sums[s8 * 128 + tid];
        smf[tid] = rsqrtf(z);
        int r = r0 + tid;
        smf[128 + tid] = g_ctm[r];
        smf[256 + tid] = g_ft[r];
        smi[384 + tid] = label[r];
    }
    __syncthreads();

    const float tad = g_t;
    const int g = lane >> 2, q = lane & 3;
#pragma unroll
    for (int mt = 0; mt < 4; mt++) {
#pragma unroll
        for (int half = 0; half < 2; half++) {
            int rl = warpM * 64 + mt * 16 + g + half * 8;
            float ctm = smf[128 + rl], ft = smf[256 + rl];
            int lab = smi[384 + rl];
            float L[8];
            float mx = -3.0e38f;
#pragma unroll
            for (int nt = 0; nt < 4; nt++) {
#pragma unroll
                for (int b = 0; b < 2; b++) {
                    int cl = warpN * 32 + nt * 8 + q * 2 + b;
                    int c = c0 + cl;
                    float Lv;
                    if (c < NCLS) {
                        float cv = acc[mt][nt][half * 2 + b] * smf[cl];
                        cv = fminf(1.f, fmaxf(-1.f, cv));
                        if (c == lab) {
                            Lv = C_S * ft;
                        } else {
                            if (cv > ctm) cv = cv * (tad + cv);
                            Lv = C_S * cv;
                        }
                        mx = fmaxf(mx, Lv);
                    } else {
                        Lv = -3.0e38f;
                    }
                    L[nt * 2 + b] = Lv;
                }
            }
            mx = fmaxf(mx, __shfl_xor_sync(0xffffffffu, mx, 1));
            mx = fmaxf(mx, __shfl_xor_sync(0xffffffffu, mx, 2));
            float s = 0.f, sl = 0.f;
#pragma unroll
            for (int j = 0; j < 8; j++) {
                if (L[j] > -1.0e38f) { s += __expf(L[j] - mx); sl += L[j]; }
            }
            s  += __shfl_xor_sync(0xffffffffu, s, 1);
            s  += __shfl_xor_sync(0xffffffffu, s, 2);
            sl += __shfl_xor_sync(0xffffffffu, sl, 1);
            sl += __shfl_xor_sync(0xffffffffu, sl, 2);
            if (q == 0) {
                smf[512  + warpN * 128 + rl] = mx;
                smf[1024 + warpN * 128 + rl] = s;
                smf[1536 + warpN * 128 + rl] = sl;
            }
        }
    }
    __syncthreads();

    if (tid < 128) {
        float m = -3.0e38f;
#pragma unroll
        for (int wn = 0; wn < 4; wn++) m = fmaxf(m, smf[512 + wn * 128 + tid]);
        float s = 0.f, sl = 0.f;
#pragma unroll
        for (int wn = 0; wn < 4; wn++) {
            float mw = smf[512 + wn * 128 + tid];
            if (mw > -1.0e38f) s += smf[1024 + wn * 128 + tid] * __expf(mw - m);
            sl += smf[1536 + wn * 128 + tid];
        }
        int slot = (r0 + tid) * CTP + blockIdx.y;
        g_pm[slot] = m;
        g_ps[slot] = s;
        g_psl[slot] = sl;
    }
}

// =================== K5: merge partials per row ===================
__global__ void k_rowreduce() {
    int r = blockIdx.x;
    int tid = threadIdx.x;
    float m = -3.0e38f, s = 0.f, sl = 0.f;
    for (int ct = tid; ct < CTP; ct += 256) {
        float m2 = g_pm[r * CTP + ct];
        float s2 = g_ps[r * CTP + ct];
        sl += g_psl[r * CTP + ct];
        if (m2 > m) { s = s * __expf(m - m2) + s2; m = m2; }
        else        { s += s2 * __expf(m2 - m); }
    }
    __shared__ float sm_m[256], sm_s[256], sm_sl[256];
    sm_m[tid] = m; sm_s[tid] = s; sm_sl[tid] = sl;
    __syncthreads();
    for (int o = 128; o; o >>= 1) {
        if (tid < o) {
            float m1 = sm_m[tid], s1 = sm_s[tid];
            float m2 = sm_m[tid + o], s2 = sm_s[tid + o];
            float M = fmaxf(m1, m2);
            sm_s[tid] = s1 * __expf(m1 - M) + s2 * __expf(m2 - M);
            sm_m[tid] = M;
            sm_sl[tid] += sm_sl[tid + o];
        }
        __syncthreads();
    }
    if (tid == 0) {
        float LSE = sm_m[0] + logf(sm_s[0]);
        float nll = LSE - C_S * g_ft[r];
        float smooth = LSE - sm_sl[0] / (float)NCLS;
        g_rowloss[r] = (1.0f - C_EPS) * nll + C_EPS * smooth;
    }
}

// =================== K6: mean ===================
__global__ void k_final(float* __restrict__ out) {
    int tid = threadIdx.x;
    float v = g_rowloss[tid];
#pragma unroll
    for (int o = 16; o; o >>= 1) v += __shfl_xor_sync(0xffffffffu, v, o);
    __shared__ float sm[16];
    if ((tid & 31) == 0) sm[tid >> 5] = v;
    __syncthreads();
    if (tid < 16) {
        float x = sm[tid];
#pragma unroll
        for (int o = 8; o; o >>= 1) x += __shfl_xor_sync(0x0000ffffu, x, o);
        if (tid == 0) out[0] = x / (float)NROW;
    }
}

// ===================================================
extern "C" void kernel_launch(void* const* d_in, const int* in_sizes, int n_in,
                              void* d_out, int out_size) {
    const float* emb = (const float*)d_in[0];
    const float* w = (const float*)d_in[1];
    const int* label = (const int*)d_in[2];
    float* out = (float*)d_out;

    cudaFuncSetAttribute(k_gemm, cudaFuncAttributeMaxDynamicSharedMemorySize, SMSZ);

    k_norm_e<<<NROW, 128>>>(emb);
    k_target<<<64, 256>>>(w, label);
    k_prep<<<1, NROW>>>();
    k_gemm<<<dim3(NRT, NCT), 256, SMSZ>>>(label, w);
    k_rowreduce<<<NROW, 256>>>();
    k_final<<<1, NROW>>>(out);
}

// round 13
// speedup vs baseline: 1.1240x; 1.0164x over previous
#include <cuda_runtime.h>
#include <cuda_bf16.h>
#include <stdint.h>
#include <math.h>

#define FEAT  512
#define NCLS  100000
#define NROW  512
#define BM    128
#define BN    128
#define NCT   782
#define NRT   4
#define CTP   782
#define CK    32
#define NCH16 16

#define C_COS_M   0.87758256189037276f
#define C_SIN_M   0.47942553860420301f
#define C_THRESH  (-0.87758256189037276f)
#define C_MM      0.23971276930210156f
#define C_S       64.0f
#define C_EPS     0.1f

// ---- scratch ----
__device__ float          g_e[NROW * FEAT];
__device__ __nv_bfloat16  g_ebfT[FEAT * NROW];   // [k][m] bf16
__device__ float g_tl[NROW];
__device__ float g_ctm[NROW];
__device__ float g_ft[NROW];
__device__ float g_t;
__device__ float g_pm[NROW * CTP];
__device__ float g_ps[NROW * CTP];
__device__ float g_psl[NROW * CTP];
__device__ float g_rowloss[NROW];

// =================== helpers ===================
__device__ __forceinline__ void cp16(uint32_t dst, const void* src) {
    asm volatile("cp.async.cg.shared.global [%0], [%1], 16;" :: "r"(dst), "l"(src));
}
__device__ __forceinline__ void cp16z(uint32_t dst, const void* src, int nbytes) {
    asm volatile("cp.async.cg.shared.global [%0], [%1], 16, %2;"
                 :: "r"(dst), "l"(src), "r"(nbytes));
}
__device__ __forceinline__ uint32_t s2u(const void* p) {
    uint32_t a;
    asm("{ .reg .u64 t; cvta.to.shared.u64 t, %1; cvt.u32.u64 %0, t; }" : "=r"(a) : "l"(p));
    return a;
}
// [k][c] bf16 tile, 256B rows; 16B-chunk XOR swizzle by k (verified rounds 9/11/12)
__device__ __forceinline__ uint32_t bswz(int k, int c) {
    return (uint32_t)(k * 256 + ((((c >> 3) ^ k) & 7) << 4) + ((c >> 3) & 8) * 16 + (c & 7) * 2);
}
__device__ __forceinline__ void ldsm4t(uint32_t* a, uint32_t addr) {
    asm volatile("ldmatrix.sync.aligned.m8n8.x4.trans.shared.b16 {%0,%1,%2,%3}, [%4];"
                 : "=r"(a[0]), "=r"(a[1]), "=r"(a[2]), "=r"(a[3]) : "r"(addr));
}
__device__ __forceinline__ void mma16816(float* c, const uint32_t* a, const uint32_t* b) {
    asm volatile(
        "mma.sync.aligned.m16n8k16.row.col.f32.bf16.bf16.f32 "
        "{%0,%1,%2,%3}, {%4,%5,%6,%7}, {%8,%9}, {%0,%1,%2,%3};"
        : "+f"(c[0]), "+f"(c[1]), "+f"(c[2]), "+f"(c[3])
        : "r"(a[0]), "r"(a[1]), "r"(a[2]), "r"(a[3]), "r"(b[0]), "r"(b[1]));
}

// =================== K1: row-normalize e (writes transposed bf16) ===================
__global__ void k_norm_e(const float* __restrict__ emb) {
    int r = blockIdx.x, t = threadIdx.x;   // 512 x 128
    float v[4], s = 0.f;
#pragma unroll
    for (int i = 0; i < 4; i++) { v[i] = emb[r * FEAT + t + i * 128]; s += v[i] * v[i]; }
#pragma unroll
    for (int o = 16; o; o >>= 1) s += __shfl_xor_sync(0xffffffffu, s, o);
    __shared__ float sm[4];
    if ((t & 31) == 0) sm[t >> 5] = s;
    __syncthreads();
    float inv = rsqrtf(sm[0] + sm[1] + sm[2] + sm[3]);
#pragma unroll
    for (int i = 0; i < 4; i++) {
        float x = v[i] * inv;
        int k = t + i * 128;
        g_e[r * FEAT + k] = x;
        g_ebfT[(size_t)k * NROW + r] = __float2bfloat16(x);
    }
}

// =================== K2: target logits + ctm/ft ===================
__global__ void k_target(const float* __restrict__ w, const int* __restrict__ label) {
    int gw = (blockIdx.x * blockDim.x + threadIdx.x) >> 5;
    int lane = threadIdx.x & 31;
    if (gw >= NROW) return;
    int lab = label[gw];
    const float* e = g_e + gw * FEAT;
    float dot = 0.f, sq = 0.f;
#pragma unroll
    for (int j = 0; j < 16; j++) {
        int k = lane + 32 * j;
        float wv = w[(size_t)k * NCLS + lab];
        dot += e[k] * wv;
        sq  += wv * wv;
    }
#pragma unroll
    for (int o = 16; o; o >>= 1) {
        dot += __shfl_xor_sync(0xffffffffu, dot, o);
        sq  += __shfl_xor_sync(0xffffffffu, sq, o);
    }
    if (lane == 0) {
        float tl = fminf(1.0f, fmaxf(-1.0f, dot * rsqrtf(sq)));
        g_tl[gw] = tl;
        float sint = sqrtf(fmaxf(0.f, 1.0f - tl * tl));
        float ctm = tl * C_COS_M - sint * C_SIN_M;
        g_ctm[gw] = ctm;
        g_ft[gw] = (tl > C_THRESH) ? ctm : (tl - C_MM);
    }
}

// =================== K3: g_t ===================
__global__ void k_prep() {
    int i = threadIdx.x;
    float s = g_tl[i];
#pragma unroll
    for (int o = 16; o; o >>= 1) s += __shfl_xor_sync(0xffffffffu, s, o);
    __shared__ float sm[16];
    if ((i & 31) == 0) sm[i >> 5] = s;
    __syncthreads();
    if (i < 16) {
        float v = sm[i];
#pragma unroll
        for (int o = 8; o; o >>= 1) v += __shfl_xor_sync(0x0000ffffu, v, o);
        if (i == 0) g_t = 0.01f * (v / (float)NROW);
    }
}

// =================== K4: fused GEMM, deep pipeline, 1 sync/iter ===================
// smem: A[k32][m128] bf16 4 stages @0 (32KB), B[k32][c128] bf16 3 stages @32K (24KB),
//       f32 staging [k32][c128] 3 stages @56K (48KB)  => 104KB
#define SM_A   0
#define SM_B   32768
#define SM_ST  57344
#define SMSZ   106496

__global__ void __launch_bounds__(256, 2) k_gemm(const int* __restrict__ label,
                                                 const float* __restrict__ w) {
    extern __shared__ char smdy[];
    uint32_t sb = s2u(smdy);
    const int tid = threadIdx.x, lane = tid & 31, wid = tid >> 5;
    const int warpM = wid >> 2;
    const int warpN = wid & 3;
    const int r0 = blockIdx.x * BM;
    const int c0 = blockIdx.y * BN;

    // load / convert mappings
    const int wk = tid >> 5;               // staging k base (k = wk + u*8)
    const int wvalid = (c0 + lane * 4 < NCLS);
    const int wbytes = wvalid ? 16 : 0;
    const size_t wcol = wvalid ? (size_t)(c0 + lane * 4) : 0;
    const int ak = tid >> 4;               // A k base (k = ak + u*16)
    const int aseg = tid & 15;             // m seg

    const uint32_t stDst = sb + SM_ST + wk * 512 + lane * 16;   // +u*4096, +st3*16384
    const uint32_t aDst  = sb + SM_A + bswz(ak, aseg * 8);      // +u*4096, +st4*8192
    const uint32_t cvDst = sb + SM_B + bswz(wk, lane * 4);      // +u*2048, +st3*8192

    // ldsm base addresses (stage 0, h 0)
    uint32_t aAddr[4], bAddr[2];
    {
        int t = lane >> 3, rr = lane & 7;
        int kkA = (t >> 1) * 8 + rr;
        int kkB = (t & 1) * 8 + rr;
#pragma unroll
        for (int mt = 0; mt < 4; mt++)
            aAddr[mt] = sb + SM_A + bswz(kkA, warpM * 64 + mt * 16 + (t & 1) * 8);
#pragma unroll
        for (int pr = 0; pr < 2; pr++)
            bAddr[pr] = sb + SM_B + bswz(kkB, warpN * 32 + pr * 16 + (t >> 1) * 8);
    }

    float acc[4][4][4];
#pragma unroll
    for (int a = 0; a < 4; a++)
#pragma unroll
        for (int b = 0; b < 4; b++)
#pragma unroll
            for (int c = 0; c < 4; c++) acc[a][b][c] = 0.f;
    float sq4[4] = {0.f, 0.f, 0.f, 0.f};

#define LOADC(chunk, st3, st4) do {                                              \
        if ((chunk) < NCH16) {                                                   \
            const float* _ws = w + (size_t)((chunk) * CK + wk) * NCLS + wcol;    \
            uint32_t _wd = stDst + (st3) * 16384;                                \
            _Pragma("unroll")                                                    \
            for (int u = 0; u < 4; u++) {                                        \
                cp16z(_wd, _ws, wbytes);                                         \
                _ws += (size_t)8 * NCLS; _wd += 4096;                            \
            }                                                                    \
            const __nv_bfloat16* _as = g_ebfT + (size_t)((chunk) * CK + ak) * NROW + r0 + aseg * 8; \
            uint32_t _ad = aDst + (st4) * 8192;                                  \
            _Pragma("unroll")                                                    \
            for (int u = 0; u < 2; u++) {                                        \
                cp16(_ad, _as);                                                  \
                _as += (size_t)16 * NROW; _ad += 4096;                           \
            }                                                                    \
        }                                                                        \
        asm volatile("cp.async.commit_group;");                                  \
    } while (0)

#define CVTC(st3) do {                                                           \
        float4 _v[4];                                                            \
        _Pragma("unroll")                                                        \
        for (int u = 0; u < 4; u++)                                              \
            _v[u] = *(const float4*)(smdy + (stDst - sb) + (st3) * 16384 + u * 4096); \
        _Pragma("unroll")                                                        \
        for (int u = 0; u < 4; u++) {                                            \
            sq4[0] += _v[u].x * _v[u].x; sq4[1] += _v[u].y * _v[u].y;            \
            sq4[2] += _v[u].z * _v[u].z; sq4[3] += _v[u].w * _v[u].w;            \
            __nv_bfloat162 _p0 = __floats2bfloat162_rn(_v[u].x, _v[u].y);        \
            __nv_bfloat162 _p1 = __floats2bfloat162_rn(_v[u].z, _v[u].w);        \
            uint2 _u2; _u2.x = *(uint32_t*)&_p0; _u2.y = *(uint32_t*)&_p1;       \
            *(uint2*)(smdy + (cvDst - sb) + (st3) * 8192 + u * 2048) = _u2;      \
        }                                                                        \
    } while (0)

    // batched fragment loads: all 6 ldsm, then 16 mma
#define MMAC(st3, st4) do {                                                      \
        _Pragma("unroll")                                                        \
        for (int h = 0; h < 2; h++) {                                            \
            uint32_t bf[2][4], af[4][4];                                         \
            ldsm4t(bf[0], bAddr[0] + (st3) * 8192 + h * 4096);                   \
            ldsm4t(bf[1], bAddr[1] + (st3) * 8192 + h * 4096);                   \
            _Pragma("unroll")                                                    \
            for (int mt = 0; mt < 4; mt++)                                       \
                ldsm4t(af[mt], aAddr[mt] + (st4) * 8192 + h * 4096);             \
            _Pragma("unroll")                                                    \
            for (int mt = 0; mt < 4; mt++) {                                     \
                mma16816(acc[mt][0], af[mt], &bf[0][0]);                         \
                mma16816(acc[mt][1], af[mt], &bf[0][2]);                         \
                mma16816(acc[mt][2], af[mt], &bf[1][0]);                         \
                mma16816(acc[mt][3], af[mt], &bf[1][2]);                         \
            }                                                                    \
        }                                                                        \
    } while (0)

    // prologue: 3 chunks in flight, convert chunk 0
    LOADC(0, 0, 0);
    LOADC(1, 1, 1);
    LOADC(2, 2, 2);
    asm volatile("cp.async.wait_group 2;");   // chunk 0 staged
    __syncthreads();
    CVTC(0);

    // st rotations: CVT target (it+1)%3, MMA B it%3, MMA A it%4, LOAD A (it+3)%4
    int stc = 1, st3m = 0, st4u = 0, st4l = 3;
#pragma unroll 1
    for (int it = 0; it < NCH16; it++) {
        asm volatile("cp.async.wait_group 1;");  // chunk it+1 staged
        __syncthreads();                          // publishes CVT(it) and retires MMA(it-1)
        if (it < NCH16 - 1) CVTC(stc);            // chunk it+1 -> B[(it+1)%3]
        LOADC(it + 3, st3m, st4l);                // refill staging[it%3], A[(it+3)%4]
        MMAC(st3m, st4u);                         // chunk it
        stc  = (stc == 2)  ? 0 : stc + 1;
        st3m = (st3m == 2) ? 0 : st3m + 1;
        st4u = (st4u + 1) & 3;
        st4l = (st4l + 1) & 3;
    }
    __syncthreads();

    // ---- column inv-norms from in-kernel sums ----
    float* sums = (float*)(smdy + SM_ST);  // [8][128]
#pragma unroll
    for (int j = 0; j < 4; j++) sums[wk * 128 + lane * 4 + j] = sq4[j];
    __syncthreads();

    float* smf = (float*)smdy;
    int*   smi = (int*)smdy;
    if (tid < 128) {
        float z = 0.f;
#pragma unroll
        for (int s8 = 0; s8 < 8; s8++) z += sums[s8 * 128 + tid];
        smf[tid] = rsqrtf(z);
        int r = r0 + tid;
        smf[128 + tid] = g_ctm[r];
        smf[256 + tid] = g_ft[r];
        smi[384 + tid] = label[r];
    }
    __syncthreads();

    const float tad = g_t;
    const int g = lane >> 2, q = lane & 3;
#pragma unroll
    for (int mt = 0; mt < 4; mt++) {
#pragma unroll
        for (int half = 0; half < 2; half++) {
            int rl = warpM * 64 + mt * 16 + g + half * 8;
            float ctm = smf[128 + rl], ft = smf[256 + rl];
            int lab = smi[384 + rl];
            float L[8];
            float mx = -3.0e38f;
#pragma unroll
            for (int nt = 0; nt < 4; nt++) {
#pragma unroll
                for (int b = 0; b < 2; b++) {
                    int cl = warpN * 32 + nt * 8 + q * 2 + b;
                    int c = c0 + cl;
                    float Lv;
                    if (c < NCLS) {
                        float cv = acc[mt][nt][half * 2 + b] * smf[cl];
                        cv = fminf(1.f, fmaxf(-1.f, cv));
                        if (c == lab) {
                            Lv = C_S * ft;
                        } else {
                            if (cv > ctm) cv = cv * (tad + cv);
                            Lv = C_S * cv;
                        }
                        mx = fmaxf(mx, Lv);
                    } else {
                        Lv = -3.0e38f;
                    }
                    L[nt * 2 + b] = Lv;
                }
            }
            mx = fmaxf(mx, __shfl_xor_sync(0xffffffffu, mx, 1));
            mx = fmaxf(mx, __shfl_xor_sync(0xffffffffu, mx, 2));
            float s = 0.f, sl = 0.f;
#pragma unroll
            for (int j = 0; j < 8; j++) {
                if (L[j] > -1.0e38f) { s += __expf(L[j] - mx); sl += L[j]; }
            }
            s  += __shfl_xor_sync(0xffffffffu, s, 1);
            s  += __shfl_xor_sync(0xffffffffu, s, 2);
            sl += __shfl_xor_sync(0xffffffffu, sl, 1);
            sl += __shfl_xor_sync(0xffffffffu, sl, 2);
            if (q == 0) {
                smf[512  + warpN * 128 + rl] = mx;
                smf[1024 + warpN * 128 + rl] = s;
                smf[1536 + warpN * 128 + rl] = sl;
            }
        }
    }
    __syncthreads();

    if (tid < 128) {
        float m = -3.0e38f;
#pragma unroll
        for (int wn = 0; wn < 4; wn++) m = fmaxf(m, smf[512 + wn * 128 + tid]);
        float s = 0.f, sl = 0.f;
#pragma unroll
        for (int wn = 0; wn < 4; wn++) {
            float mw = smf[512 + wn * 128 + tid];
            if (mw > -1.0e38f) s += smf[1024 + wn * 128 + tid] * __expf(mw - m);
            sl += smf[1536 + wn * 128 + tid];
        }
        int slot = (r0 + tid) * CTP + blockIdx.y;
        g_pm[slot] = m;
        g_ps[slot] = s;
        g_psl[slot] = sl;
    }
}

// =================== K5: merge partials per row ===================
__global__ void k_rowreduce() {
    int r = blockIdx.x;
    int tid = threadIdx.x;
    float m = -3.0e38f, s = 0.f, sl = 0.f;
    for (int ct = tid; ct < CTP; ct += 256) {
        float m2 = g_pm[r * CTP + ct];
        float s2 = g_ps[r * CTP + ct];
        sl += g_psl[r * CTP + ct];
        if (m2 > m) { s = s * __expf(m - m2) + s2; m = m2; }
        else        { s += s2 * __expf(m2 - m); }
    }
    __shared__ float sm_m[256], sm_s[256], sm_sl[256];
    sm_m[tid] = m; sm_s[tid] = s; sm_sl[tid] = sl;
    __syncthreads();
    for (int o = 128; o; o >>= 1) {
        if (tid < o) {
            float m1 = sm_m[tid], s1 = sm_s[tid];
            float m2 = sm_m[tid + o], s2 = sm_s[tid + o];
            float M = fmaxf(m1, m2);
            sm_s[tid] = s1 * __expf(m1 - M) + s2 * __expf(m2 - M);
            sm_m[tid] = M;
            sm_sl[tid] += sm_sl[tid + o];
        }
        __syncthreads();
    }
    if (tid == 0) {
        float LSE = sm_m[0] + logf(sm_s[0]);
        float nll = LSE - C_S * g_ft[r];
        float smooth = LSE - sm_sl[0] / (float)NCLS;
        g_rowloss[r] = (1.0f - C_EPS) * nll + C_EPS * smooth;
    }
}

// =================== K6: mean ===================
__global__ void k_final(float* __restrict__ out) {
    int tid = threadIdx.x;
    float v = g_rowloss[tid];
#pragma unroll
    for (int o = 16; o; o >>= 1) v += __shfl_xor_sync(0xffffffffu, v, o);
    __shared__ float sm[16];
    if ((tid & 31) == 0) sm[tid >> 5] = v;
    __syncthreads();
    if (tid < 16) {
        float x = sm[tid];
#pragma unroll
        for (int o = 8; o; o >>= 1) x += __shfl_xor_sync(0x0000ffffu, x, o);
        if (tid == 0) out[0] = x / (float)NROW;
    }
}

// ===================================================
extern "C" void kernel_launch(void* const* d_in, const int* in_sizes, int n_in,
                              void* d_out, int out_size) {
    const float* emb = (const float*)d_in[0];
    const float* w = (const float*)d_in[1];
    const int* label = (const int*)d_in[2];
    float* out = (float*)d_out;

    cudaFuncSetAttribute(k_gemm, cudaFuncAttributeMaxDynamicSharedMemorySize, SMSZ);

    k_norm_e<<<NROW, 128>>>(emb);
    k_target<<<64, 256>>>(w, label);
    k_prep<<<1, NROW>>>();
    k_gemm<<<dim3(NRT, NCT), 256, SMSZ>>>(label, w);
    k_rowreduce<<<NROW, 256>>>();
    k_final<<<1, NROW>>>(out);
}